// round 4
// baseline (speedup 1.0000x reference)
#include <cuda_runtime.h>
#include <cuda_fp16.h>
#include <cstdint>

#define IN_F  4096
#define OUT_F 4096
#define NFAC  3

// ---------------- scratch (device globals; allocation forbidden) -----------
__device__ __align__(1024) float  g_Q[NFAC * 64 * 64 * 64];
__device__ int    g_pinv[NFAC * IN_F];
__device__ __align__(1024) float  g_w0[(size_t)OUT_F * IN_F];        // 64 MB
__device__ __align__(1024) float  g_w1[(size_t)OUT_F * IN_F];        // 64 MB
__device__ __align__(1024) __half g_wh[(size_t)OUT_F * IN_F];        // 32 MB
__device__ __align__(1024) __half g_xh[(size_t)8 * 2048 * IN_F];     // 128 MB

// ---------------- helpers ---------------------------------------------------
__device__ __forceinline__ uint32_t smem_u32(const void* p) {
    uint32_t a;
    asm("{ .reg .u64 t; cvta.to.shared.u64 t, %1; cvt.u32.u64 %0, t; }" : "=r"(a) : "l"(p));
    return a;
}
#define CP_ASYNC16(dst, src) \
    asm volatile("cp.async.cg.shared.global [%0], [%1], 16;" :: "r"(dst), "l"(src) : "memory")
#define CP_COMMIT()  asm volatile("cp.async.commit_group;" ::: "memory")
#define CP_WAIT2()   asm volatile("cp.async.wait_group 2;" ::: "memory")

#define LDSM4(r, addr) \
    asm volatile("ldmatrix.sync.aligned.m8n8.x4.shared.b16 {%0,%1,%2,%3}, [%4];" \
        : "=r"((r)[0]), "=r"((r)[1]), "=r"((r)[2]), "=r"((r)[3]) : "r"(addr))

#define MMA16816(c, a, b0v, b1v) \
    asm volatile("mma.sync.aligned.m16n8k16.row.col.f32.f16.f16.f32 " \
        "{%0,%1,%2,%3},{%4,%5,%6,%7},{%8,%9},{%0,%1,%2,%3};" \
        : "+f"((c)[0]), "+f"((c)[1]), "+f"((c)[2]), "+f"((c)[3]) \
        : "r"((a)[0]), "r"((a)[1]), "r"((a)[2]), "r"((a)[3]), "r"(b0v), "r"(b1v))

// ---------------- Cayley: Q = (I-S)(I+S)^-1 via GJ on [I-S | I+S] ----------
__global__ void cayley_kernel(const float* __restrict__ R_all)
{
    __shared__ float aug[64][129];
    const int m   = blockIdx.x;
    const float* R = R_all + (size_t)m * 4096;
    const int tid = threadIdx.x;

    for (int idx = tid; idx < 4096; idx += 256) {
        int i = idx >> 6, j = idx & 63;
        float s = 0.5f * (R[i * 64 + j] - R[j * 64 + i]);
        float d = (i == j) ? 1.0f : 0.0f;
        aug[i][j]      = d - s;
        aug[i][64 + j] = d + s;
    }
    __syncthreads();

    const int r  = tid >> 2;
    const int c0 = tid & 3;
    for (int k = 0; k < 64; k++) {
        float inv = 1.0f / aug[k][k];
        __syncthreads();
        if (tid < 32) {
            #pragma unroll
            for (int i = 0; i < 4; i++) aug[k][tid + 32 * i] *= inv;
        }
        __syncthreads();
        float f = aug[r][k];
        __syncthreads();
        if (r != k) {
            #pragma unroll
            for (int i = 0; i < 32; i++) {
                int c = c0 + 4 * i;
                aug[r][c] -= f * aug[k][c];
            }
        }
        __syncthreads();
    }

    float* Qm = g_Q + (size_t)m * 4096;
    for (int idx = tid; idx < 4096; idx += 256) {
        int a = idx >> 6, b = idx & 63;
        Qm[a * 64 + b] = aug[b][64 + a];
    }
}

// ---------------- inverse permutation ----------------
__global__ void pinv_kernel(const int* __restrict__ perm)
{
    int f = blockIdx.y;
    int j = blockIdx.x * 256 + threadIdx.x;
    g_pinv[f * IN_F + perm[f * IN_F + j]] = j;
}

// ---------------- x -> fp16 ----------------
__global__ void convert_x(const float4* __restrict__ in, uint4* __restrict__ out)
{
    int i = blockIdx.x * 256 + threadIdx.x;
    float4 a = in[2 * i], b = in[2 * i + 1];
    __half2 h0 = __floats2half2_rn(a.x, a.y);
    __half2 h1 = __floats2half2_rn(a.z, a.w);
    __half2 h2 = __floats2half2_rn(b.x, b.y);
    __half2 h3 = __floats2half2_rn(b.z, b.w);
    uint4 v;
    v.x = *(uint32_t*)&h0; v.y = *(uint32_t*)&h1;
    v.z = *(uint32_t*)&h2; v.w = *(uint32_t*)&h3;
    out[i] = v;
}

// ---------------- one butterfly factor applied to W columns ----------------
// Wout[r, cs[a]] = sum_b Q[f,d,a,b] * Win[r, cs[b]]  (last pass: *s -> fp16)
// Register-tiled: thread = 4 a-cols x 8 rows. Q stored transposed in smem.
#define ROT_SMEM (64*68*4 + 128*68*4 + 64*4 + 128*4)   // Qt + Ts + cs + sv

__global__ __launch_bounds__(256) void rot_kernel(
    const float* __restrict__ Win, float* __restrict__ Wout,
    __half* __restrict__ Wh, int factor, const float* __restrict__ s)
{
    extern __shared__ char sm[];
    float (*Qt)[68] = (float (*)[68])sm;                    // [64][68], Qt[b][a]
    float (*Ts)[68] = (float (*)[68])(sm + 64 * 68 * 4);    // [128][68]
    int*   cs = (int*)(sm + (64 + 128) * 68 * 4);
    float* sv = (float*)(cs + 64);

    const int d   = blockIdx.x;
    const int rg  = blockIdx.y;
    const int tid = threadIdx.x;
    const int row0 = rg * 128;

    const float* Qm = g_Q + ((size_t)factor * 64 + d) * 4096;
    for (int idx = tid; idx < 4096; idx += 256) {
        int a = idx >> 6, b = idx & 63;
        Qt[b][a] = Qm[idx];
    }
    if (tid < 64) cs[tid] = g_pinv[factor * IN_F + d * 64 + tid];
    if (s && tid < 128) sv[tid] = s[row0 + tid];
    __syncthreads();

    #pragma unroll
    for (int i = 0; i < 8; i++) {
        int q = tid + 256 * i;                // 2048 float4 chunks
        int rr = q >> 4, b0 = (q & 15) * 4;
        // pinv moves 32-aligned runs of 32 -> float4 gather contiguous
        *(float4*)&Ts[rr][b0] = *(const float4*)&Win[(size_t)(row0 + rr) * IN_F + cs[b0]];
    }
    __syncthreads();

    const int tx = tid & 15, ty = tid >> 4;
    const int a0 = tx * 4,   r0 = ty * 8;

    float acc[8][4];
    #pragma unroll
    for (int j = 0; j < 8; j++)
        #pragma unroll
        for (int i = 0; i < 4; i++) acc[j][i] = 0.0f;

    for (int b4 = 0; b4 < 16; b4++) {
        float qa[4][4];
        #pragma unroll
        for (int k = 0; k < 4; k++)
            *(float4*)&qa[k][0] = *(const float4*)&Qt[b4 * 4 + k][a0];
        #pragma unroll
        for (int j = 0; j < 8; j++) {
            float4 t = *(const float4*)&Ts[r0 + j][b4 * 4];
            #pragma unroll
            for (int i = 0; i < 4; i++)
                acc[j][i] += qa[0][i] * t.x + qa[1][i] * t.y
                           + qa[2][i] * t.z + qa[3][i] * t.w;
        }
    }
    __syncthreads();                       // all Ts reads done

    #pragma unroll
    for (int j = 0; j < 8; j++)
        *(float4*)&Ts[r0 + j][a0] = *(float4*)&acc[j][0];   // stage result
    __syncthreads();

    if (s == nullptr) {
        #pragma unroll
        for (int i = 0; i < 8; i++) {
            int q = tid + 256 * i;
            int rr = q >> 4, b0 = (q & 15) * 4;
            *(float4*)&Wout[(size_t)(row0 + rr) * IN_F + cs[b0]] = *(float4*)&Ts[rr][b0];
        }
    } else {
        #pragma unroll
        for (int i = 0; i < 8; i++) {
            int q = tid + 256 * i;
            int rr = q >> 4, b0 = (q & 15) * 4;
            float4 v = *(float4*)&Ts[rr][b0];
            float sc = sv[rr];
            __half2 h0 = __floats2half2_rn(v.x * sc, v.y * sc);
            __half2 h1 = __floats2half2_rn(v.z * sc, v.w * sc);
            uint2 u;
            u.x = *(uint32_t*)&h0; u.y = *(uint32_t*)&h1;
            *(uint2*)&Wh[(size_t)(row0 + rr) * IN_F + cs[b0]] = u;
        }
    }
}

// ---------------- fp16 mma.sync GEMM: C[16384,4096] = A * B^T + bias -------
// CTA 128x256, 8 warps (2x4), warp tile 64x64, BK=64 halves, 4 stages.
#define BKH 64
#define AST 16384                       // 128 x 64 halves
#define BST 32768                       // 256 x 64 halves
#define STG (AST + BST)                 // 49152
#define STAGES 4
#define SMEM_TOTAL (STAGES * STG)       // 196608

__global__ __launch_bounds__(256, 1) void gemm_hmma(
    const __half* __restrict__ A, const __half* __restrict__ B,
    const float* __restrict__ bias, float* __restrict__ C)
{
    extern __shared__ char smem[];
    const uint32_t sb = smem_u32(smem);
    const int tid = threadIdx.x;
    const int wid = tid >> 5, lid = tid & 31;
    const int wm  = wid >> 2, wn = wid & 3;       // 2 x 4 warps; warp tile 64x64
    const int m0  = blockIdx.y * 128;
    const int n0  = blockIdx.x * 256;

    float acc[4][4][2][4];    // [mi][g][j(n8)][frag]
    #pragma unroll
    for (int mi = 0; mi < 4; mi++)
        #pragma unroll
        for (int g = 0; g < 4; g++)
            #pragma unroll
            for (int j = 0; j < 2; j++)
                #pragma unroll
                for (int k = 0; k < 4; k++) acc[mi][g][j][k] = 0.0f;

    auto load_stage = [&](int st, int kt) {
        const uint32_t ab = sb + st * STG;
        const uint32_t bb = ab + AST;
        const __half* Ag = A + (size_t)m0 * IN_F + kt * BKH;
        const __half* Bg = B + (size_t)n0 * IN_F + kt * BKH;
        #pragma unroll
        for (int i = 0; i < 4; i++) {
            int q = tid + 256 * i;                 // 1024 x 16B
            int r = q >> 3, c = q & 7;
            CP_ASYNC16(ab + r * 128 + ((c ^ (r & 7)) << 4), Ag + (size_t)r * IN_F + c * 8);
        }
        #pragma unroll
        for (int i = 0; i < 8; i++) {              // 2048 x 16B
            int q = tid + 256 * i;
            int r = q >> 3, c = q & 7;
            CP_ASYNC16(bb + r * 128 + ((c ^ (r & 7)) << 4), Bg + (size_t)r * IN_F + c * 8);
        }
    };

    load_stage(0, 0); CP_COMMIT();
    load_stage(1, 1); CP_COMMIT();
    load_stage(2, 2); CP_COMMIT();

    const int lrow = (lid & 7) + ((lid >> 3) & 1) * 8;   // 0..15
    const int lkhi = (lid >> 4) & 1;
    const int rowx = lrow & 7;

    const int NK = IN_F / BKH;    // 64
    for (int kt = 0; kt < NK; kt++) {
        CP_WAIT2();
        __syncthreads();
        const uint32_t as = sb + (kt & 3) * STG;
        const uint32_t bs = as + AST;
        const uint32_t a_base = as + (wm * 64 + lrow) * 128;
        const uint32_t b_base = bs + (wn * 64 + lrow) * 128;

        #pragma unroll
        for (int kk = 0; kk < 4; kk++) {
            const uint32_t coff = ((((kk << 1) | lkhi) ^ rowx) << 4);
            uint32_t afr[4][4];
            #pragma unroll
            for (int mi = 0; mi < 4; mi++)
                LDSM4(afr[mi], a_base + mi * 2048 + coff);
            uint32_t bfr[4][4];
            #pragma unroll
            for (int g = 0; g < 4; g++)
                LDSM4(bfr[g], b_base + g * 2048 + coff);
            #pragma unroll
            for (int mi = 0; mi < 4; mi++)
                #pragma unroll
                for (int g = 0; g < 4; g++) {
                    MMA16816(acc[mi][g][0], afr[mi], bfr[g][0], bfr[g][2]);
                    MMA16816(acc[mi][g][1], afr[mi], bfr[g][1], bfr[g][3]);
                }
        }

        if (kt + 3 < NK) load_stage((kt + 3) & 3, kt + 3);
        CP_COMMIT();    // one commit per iter keeps wait_group count aligned
    }

    // epilogue: fused bias, float2 stores
    const int mrow = lid >> 2;
    const int ncl  = (lid & 3) * 2;
    #pragma unroll
    for (int g = 0; g < 4; g++)
        #pragma unroll
        for (int j = 0; j < 2; j++) {
            int n = n0 + wn * 64 + g * 16 + j * 8 + ncl;
            float2 bv = *(const float2*)&bias[n];
            #pragma unroll
            for (int mi = 0; mi < 4; mi++) {
                int m = m0 + wm * 64 + mi * 16 + mrow;
                float* a4 = acc[mi][g][j];
                float2 v0 = { a4[0] + bv.x, a4[1] + bv.y };
                float2 v1 = { a4[2] + bv.x, a4[3] + bv.y };
                *(float2*)&C[(size_t)m * OUT_F + n]       = v0;
                *(float2*)&C[(size_t)(m + 8) * OUT_F + n] = v1;
            }
        }
}

// ---------------- launch ----------------
extern "C" void kernel_launch(void* const* d_in, const int* in_sizes, int n_in,
                              void* d_out, int out_size)
{
    const float* x      = (const float*)d_in[0];
    const float* weight = (const float*)d_in[1];
    const float* bias   = (const float*)d_in[2];
    const float* boft_R = (const float*)d_in[3];
    const float* boft_s = (const float*)d_in[4];
    const int*   perm   = (const int*)d_in[5];
    float* out = (float*)d_out;

    float *w0, *w1; __half *wh, *xh;
    cudaGetSymbolAddress((void**)&w0, g_w0);
    cudaGetSymbolAddress((void**)&w1, g_w1);
    cudaGetSymbolAddress((void**)&wh, g_wh);
    cudaGetSymbolAddress((void**)&xh, g_xh);

    cayley_kernel<<<192, 256>>>(boft_R);
    pinv_kernel<<<dim3(16, 3), 256>>>(perm);
    convert_x<<<32768, 256>>>((const float4*)x, (uint4*)xh);

    cudaFuncSetAttribute(rot_kernel, cudaFuncAttributeMaxDynamicSharedMemorySize, ROT_SMEM);
    rot_kernel<<<dim3(64, 32), 256, ROT_SMEM>>>(weight, w0, nullptr, 0, nullptr);
    rot_kernel<<<dim3(64, 32), 256, ROT_SMEM>>>(w0,     w1, nullptr, 1, nullptr);
    rot_kernel<<<dim3(64, 32), 256, ROT_SMEM>>>(w1, nullptr, wh,     2, boft_s);

    cudaFuncSetAttribute(gemm_hmma, cudaFuncAttributeMaxDynamicSharedMemorySize, SMEM_TOTAL);
    gemm_hmma<<<dim3(OUT_F / 256, 16384 / 128), 256, SMEM_TOTAL>>>(xh, wh, bias, out);
}

// round 5
// speedup vs baseline: 1.0685x; 1.0685x over previous
#include <cuda_runtime.h>
#include <cuda_fp16.h>
#include <cstdint>

#define IN_F  4096
#define OUT_F 4096
#define NFAC  3

// ---------------- scratch (device globals; allocation forbidden) -----------
__device__ __align__(1024) float  g_Q[NFAC * 64 * 64 * 64];
__device__ int    g_pinv[NFAC * IN_F];
__device__ __align__(1024) float  g_w0[(size_t)OUT_F * IN_F];        // 64 MB
__device__ __align__(1024) float  g_w1[(size_t)OUT_F * IN_F];        // 64 MB
__device__ __align__(1024) __half g_wh[(size_t)OUT_F * IN_F];        // 32 MB
__device__ __align__(1024) __half g_xh[(size_t)8 * 2048 * IN_F];     // 128 MB

// ---------------- helpers ---------------------------------------------------
__device__ __forceinline__ uint32_t smem_u32(const void* p) {
    uint32_t a;
    asm("{ .reg .u64 t; cvta.to.shared.u64 t, %1; cvt.u32.u64 %0, t; }" : "=r"(a) : "l"(p));
    return a;
}
#define CP_ASYNC16(dst, src) \
    asm volatile("cp.async.cg.shared.global [%0], [%1], 16;" :: "r"(dst), "l"(src) : "memory")
#define CP_COMMIT()  asm volatile("cp.async.commit_group;" ::: "memory")
#define CP_WAIT1()   asm volatile("cp.async.wait_group 1;" ::: "memory")

#define LDSM4(r, addr) \
    asm volatile("ldmatrix.sync.aligned.m8n8.x4.shared.b16 {%0,%1,%2,%3}, [%4];" \
        : "=r"((r)[0]), "=r"((r)[1]), "=r"((r)[2]), "=r"((r)[3]) : "r"(addr))

#define MMA16816(c, a, b0v, b1v) \
    asm volatile("mma.sync.aligned.m16n8k16.row.col.f32.f16.f16.f32 " \
        "{%0,%1,%2,%3},{%4,%5,%6,%7},{%8,%9},{%0,%1,%2,%3};" \
        : "+f"((c)[0]), "+f"((c)[1]), "+f"((c)[2]), "+f"((c)[3]) \
        : "r"((a)[0]), "r"((a)[1]), "r"((a)[2]), "r"((a)[3]), "r"(b0v), "r"(b1v))

// ---------------- Cayley: Q = (I-S)(I+S)^-1 via GJ on [I-S | I+S] ----------
__global__ void cayley_kernel(const float* __restrict__ R_all)
{
    __shared__ float aug[64][129];
    const int m   = blockIdx.x;
    const float* R = R_all + (size_t)m * 4096;
    const int tid = threadIdx.x;

    for (int idx = tid; idx < 4096; idx += 256) {
        int i = idx >> 6, j = idx & 63;
        float s = 0.5f * (R[i * 64 + j] - R[j * 64 + i]);
        float d = (i == j) ? 1.0f : 0.0f;
        aug[i][j]      = d - s;
        aug[i][64 + j] = d + s;
    }
    __syncthreads();

    const int r  = tid >> 2;
    const int c0 = tid & 3;
    for (int k = 0; k < 64; k++) {
        float inv = 1.0f / aug[k][k];
        __syncthreads();
        if (tid < 32) {
            #pragma unroll
            for (int i = 0; i < 4; i++) aug[k][tid + 32 * i] *= inv;
        }
        __syncthreads();
        float f = aug[r][k];
        __syncthreads();
        if (r != k) {
            #pragma unroll
            for (int i = 0; i < 32; i++) {
                int c = c0 + 4 * i;
                aug[r][c] -= f * aug[k][c];
            }
        }
        __syncthreads();
    }

    float* Qm = g_Q + (size_t)m * 4096;
    for (int idx = tid; idx < 4096; idx += 256) {
        int a = idx >> 6, b = idx & 63;
        Qm[a * 64 + b] = aug[b][64 + a];
    }
}

// ---------------- inverse permutation ----------------
__global__ void pinv_kernel(const int* __restrict__ perm)
{
    int f = blockIdx.y;
    int j = blockIdx.x * 256 + threadIdx.x;
    g_pinv[f * IN_F + perm[f * IN_F + j]] = j;
}

// ---------------- x -> fp16 ----------------
__global__ void convert_x(const float4* __restrict__ in, uint4* __restrict__ out)
{
    int i = blockIdx.x * 256 + threadIdx.x;
    float4 a = in[2 * i], b = in[2 * i + 1];
    __half2 h0 = __floats2half2_rn(a.x, a.y);
    __half2 h1 = __floats2half2_rn(a.z, a.w);
    __half2 h2 = __floats2half2_rn(b.x, b.y);
    __half2 h3 = __floats2half2_rn(b.z, b.w);
    uint4 v;
    v.x = *(uint32_t*)&h0; v.y = *(uint32_t*)&h1;
    v.z = *(uint32_t*)&h2; v.w = *(uint32_t*)&h3;
    out[i] = v;
}

// ---------------- one butterfly factor applied to W columns (R3 version) ---
// Wout[r, cs[a]] = sum_b Q[f,d,a,b] * Win[r, cs[b]]
__global__ __launch_bounds__(256) void rot_kernel(
    const float* __restrict__ Win, float* __restrict__ Wout,
    __half* __restrict__ Wh, int factor, const float* __restrict__ s)
{
    __shared__ float Qs[64][68];
    __shared__ float Ts[64][68];
    __shared__ int   cs[64];

    const int d   = blockIdx.x;
    const int rg  = blockIdx.y;
    const int tid = threadIdx.x;

    const float* Qm = g_Q + ((size_t)factor * 64 + d) * 4096;
    #pragma unroll
    for (int i = 0; i < 4; i++) {
        int q = tid + 256 * i;
        int row = q >> 4, c4 = (q & 15) * 4;
        *(float4*)&Qs[row][c4] = *(const float4*)&Qm[row * 64 + c4];
    }
    if (tid < 64) cs[tid] = g_pinv[factor * IN_F + d * 64 + tid];
    __syncthreads();

    const int row0 = rg * 64;
    #pragma unroll
    for (int i = 0; i < 4; i++) {
        int q = tid + 256 * i;
        int rr = q >> 4, b0 = (q & 15) * 4;
        *(float4*)&Ts[rr][b0] = *(const float4*)&Win[(size_t)(row0 + rr) * IN_F + cs[b0]];
    }
    __syncthreads();

    const int a  = tid & 63;
    const int r0 = tid >> 6;
    float acc[16];
    #pragma unroll
    for (int j = 0; j < 16; j++) acc[j] = 0.0f;

    for (int b4 = 0; b4 < 16; b4++) {
        float4 q = *(const float4*)&Qs[a][b4 * 4];
        #pragma unroll
        for (int j = 0; j < 16; j++) {
            float4 t = *(const float4*)&Ts[r0 * 16 + j][b4 * 4];
            acc[j] += q.x * t.x + q.y * t.y + q.z * t.z + q.w * t.w;
        }
    }

    const int col = cs[a];
    #pragma unroll
    for (int j = 0; j < 16; j++) {
        int rr = row0 + r0 * 16 + j;
        if (s) Wh[(size_t)rr * IN_F + col] = __float2half_rn(acc[j] * s[rr]);
        else   Wout[(size_t)rr * IN_F + col] = acc[j];
    }
}

// ---------------- fp16 mma.sync GEMM: C[16384,4096] = A * B^T + bias -------
// CTA 128x128, 4 warps (2x2), warp tile 64x64, BK=64 halves, 3 stages,
// 96 KB smem -> 2 CTAs/SM.
#define BKH 64
#define AST 16384                       // 128 x 64 halves
#define STG 32768                       // A + B per stage
#define STAGES 3
#define SMEM_TOTAL (STAGES * STG)       // 98304

__global__ __launch_bounds__(128, 2) void gemm_hmma(
    const __half* __restrict__ A, const __half* __restrict__ B,
    const float* __restrict__ bias, float* __restrict__ C)
{
    extern __shared__ char smem[];
    const uint32_t sb = smem_u32(smem);
    const int tid = threadIdx.x;
    const int wid = tid >> 5, lid = tid & 31;
    const int wm  = wid >> 1, wn = wid & 1;       // 2x2 warps; warp tile 64x64
    const int m0  = blockIdx.y * 128;
    const int n0  = blockIdx.x * 128;

    float acc[4][4][2][4];    // [mi][g][j(n8)][frag]
    #pragma unroll
    for (int mi = 0; mi < 4; mi++)
        #pragma unroll
        for (int g = 0; g < 4; g++)
            #pragma unroll
            for (int j = 0; j < 2; j++)
                #pragma unroll
                for (int k = 0; k < 4; k++) acc[mi][g][j][k] = 0.0f;

    auto load_stage = [&](int st, int kt) {
        const uint32_t ab = sb + st * STG;
        const uint32_t bb = ab + AST;
        const __half* Ag = A + (size_t)m0 * IN_F + kt * BKH;
        const __half* Bg = B + (size_t)n0 * IN_F + kt * BKH;
        #pragma unroll
        for (int i = 0; i < 8; i++) {              // A: 1024 x 16B
            int q = tid + 128 * i;
            int r = q >> 3, c = q & 7;
            CP_ASYNC16(ab + r * 128 + ((c ^ (r & 7)) << 4), Ag + (size_t)r * IN_F + c * 8);
        }
        #pragma unroll
        for (int i = 0; i < 8; i++) {              // B: 1024 x 16B
            int q = tid + 128 * i;
            int r = q >> 3, c = q & 7;
            CP_ASYNC16(bb + r * 128 + ((c ^ (r & 7)) << 4), Bg + (size_t)r * IN_F + c * 8);
        }
    };

    load_stage(0, 0); CP_COMMIT();
    load_stage(1, 1); CP_COMMIT();

    const int lrow = (lid & 7) + ((lid >> 3) & 1) * 8;   // 0..15
    const int lkhi = (lid >> 4) & 1;
    const int rowx = lrow & 7;

    const int NK = IN_F / BKH;    // 64
    for (int kt = 0; kt < NK; kt++) {
        CP_WAIT1();
        __syncthreads();
        const uint32_t as = sb + (kt % STAGES) * STG;
        const uint32_t bs = as + AST;
        const uint32_t a_base = as + (wm * 64 + lrow) * 128;
        const uint32_t b_base = bs + (wn * 64 + lrow) * 128;

        #pragma unroll
        for (int kk = 0; kk < 4; kk++) {
            const uint32_t coff = ((((kk << 1) | lkhi) ^ rowx) << 4);
            uint32_t afr[4][4];
            #pragma unroll
            for (int mi = 0; mi < 4; mi++)
                LDSM4(afr[mi], a_base + mi * 2048 + coff);
            uint32_t bfr[4][4];
            #pragma unroll
            for (int g = 0; g < 4; g++)
                LDSM4(bfr[g], b_base + g * 2048 + coff);
            #pragma unroll
            for (int mi = 0; mi < 4; mi++)
                #pragma unroll
                for (int g = 0; g < 4; g++) {
                    MMA16816(acc[mi][g][0], afr[mi], bfr[g][0], bfr[g][2]);
                    MMA16816(acc[mi][g][1], afr[mi], bfr[g][1], bfr[g][3]);
                }
        }

        if (kt + 2 < NK) load_stage((kt + 2) % STAGES, kt + 2);
        CP_COMMIT();    // one commit per iter keeps wait_group count aligned
    }

    // epilogue: fused bias, float2 stores
    const int mrow = lid >> 2;
    const int ncl  = (lid & 3) * 2;
    #pragma unroll
    for (int g = 0; g < 4; g++)
        #pragma unroll
        for (int j = 0; j < 2; j++) {
            int n = n0 + wn * 64 + g * 16 + j * 8 + ncl;
            float2 bv = *(const float2*)&bias[n];
            #pragma unroll
            for (int mi = 0; mi < 4; mi++) {
                int m = m0 + wm * 64 + mi * 16 + mrow;
                float* a4 = acc[mi][g][j];
                float2 v0 = { a4[0] + bv.x, a4[1] + bv.y };
                float2 v1 = { a4[2] + bv.x, a4[3] + bv.y };
                *(float2*)&C[(size_t)m * OUT_F + n]       = v0;
                *(float2*)&C[(size_t)(m + 8) * OUT_F + n] = v1;
            }
        }
}

// ---------------- launch ----------------
extern "C" void kernel_launch(void* const* d_in, const int* in_sizes, int n_in,
                              void* d_out, int out_size)
{
    const float* x      = (const float*)d_in[0];
    const float* weight = (const float*)d_in[1];
    const float* bias   = (const float*)d_in[2];
    const float* boft_R = (const float*)d_in[3];
    const float* boft_s = (const float*)d_in[4];
    const int*   perm   = (const int*)d_in[5];
    float* out = (float*)d_out;

    float *w0, *w1; __half *wh, *xh;
    cudaGetSymbolAddress((void**)&w0, g_w0);
    cudaGetSymbolAddress((void**)&w1, g_w1);
    cudaGetSymbolAddress((void**)&wh, g_wh);
    cudaGetSymbolAddress((void**)&xh, g_xh);

    cayley_kernel<<<192, 256>>>(boft_R);
    pinv_kernel<<<dim3(16, 3), 256>>>(perm);
    convert_x<<<32768, 256>>>((const float4*)x, (uint4*)xh);

    rot_kernel<<<dim3(64, 64), 256>>>(weight, w0, nullptr, 0, nullptr);
    rot_kernel<<<dim3(64, 64), 256>>>(w0,     w1, nullptr, 1, nullptr);
    rot_kernel<<<dim3(64, 64), 256>>>(w1, nullptr, wh,     2, boft_s);

    cudaFuncSetAttribute(gemm_hmma, cudaFuncAttributeMaxDynamicSharedMemorySize, SMEM_TOTAL);
    gemm_hmma<<<dim3(OUT_F / 128, 16384 / 128), 128, SMEM_TOTAL>>>(xh, wh, bias, out);
}